// round 14
// baseline (speedup 1.0000x reference)
#include <cuda_runtime.h>
#include <cuda_bf16.h>
#include <cstdint>

// out[b,a,f] = (a < M[b]) * relu( resid[b,a,:] @ w[:,f] + node[b,a,f] )
// B=4096, A=128, K=RF=128, F=128 fp32.
// mma.sync m16n8k16 bf16, 3-pass split D = Ah*Bh + Al*Bh + Ah*Bl (fp32 accum).
// 512 thr/CTA. Adaptive warp tiling (ncg in {2,4,8}) + dynamic work stealing
// via global atomic counter (prefetched one iteration ahead).
// resid: double-buffered cp.async raw tile. node: direct LDG epilogue.

#define A_DIM 128
#define F_DIM 128
#define K_DIM 128

#define RPITCH 560                 // 140 floats: row bank-starts all distinct
#define SM_R0  0
#define SM_R1  71680               // 128*560
#define SM_BH  143360
#define SM_BL  184320
#define SM_CTRL 225280             // 2 int slots (next-molecule id, parity-indexed)
#define SMEM_TOTAL 225296

__device__ int g_next;

__global__ void reset_next(int v) {
    if (threadIdx.x == 0 && blockIdx.x == 0) g_next = v;
}

__device__ __forceinline__ uint32_t smem_u32(const void* p) {
    uint32_t a;
    asm("{ .reg .u64 t; cvta.to.shared.u64 t, %1; cvt.u32.u64 %0, t; }" : "=r"(a) : "l"(p));
    return a;
}
__device__ __forceinline__ uint32_t pack2h(float x, float y) {
    __nv_bfloat162 p(__float2bfloat16(x), __float2bfloat16(y));
    return *(uint32_t*)&p;
}
__device__ __forceinline__ uint32_t pack2l(float x, float y) {
    __nv_bfloat16 hx = __float2bfloat16(x), hy = __float2bfloat16(y);
    __nv_bfloat162 p(__float2bfloat16(x - __bfloat162float(hx)),
                     __float2bfloat16(y - __bfloat162float(hy)));
    return *(uint32_t*)&p;
}

#define LDS128(r0, r1, r2, r3, addr) \
    asm volatile("ld.shared.v4.b32 {%0,%1,%2,%3}, [%4];" \
                 : "=r"(r0), "=r"(r1), "=r"(r2), "=r"(r3) : "r"(addr))
#define LDS64F(f0, f1, addr) \
    asm volatile("ld.shared.v2.f32 {%0,%1}, [%2];" : "=f"(f0), "=f"(f1) : "r"(addr))
#define CP_ASYNC16(dst, src) \
    asm volatile("cp.async.cg.shared.global [%0], [%1], 16;" :: "r"(dst), "l"(src))
#define CP_COMMIT() asm volatile("cp.async.commit_group;" ::: "memory")
#define CP_WAIT1()  asm volatile("cp.async.wait_group 1;" ::: "memory")

__device__ __forceinline__ void mma_bf16(float* c, const uint32_t* a,
                                         uint32_t b0, uint32_t b1) {
    asm volatile(
        "mma.sync.aligned.m16n8k16.row.col.f32.bf16.bf16.f32 "
        "{%0,%1,%2,%3}, {%4,%5,%6,%7}, {%8,%9}, {%0,%1,%2,%3};"
        : "+f"(c[0]), "+f"(c[1]), "+f"(c[2]), "+f"(c[3])
        : "r"(a[0]), "r"(a[1]), "r"(a[2]), "r"(a[3]), "r"(b0), "r"(b1));
}

// One warp computes + stores a 16-row x NBC*8-col unit.
template<int NBC>
__device__ __forceinline__ void unit_compute(
    uint32_t smb, uint32_t rbuf_off, int lane, int mb, int cq, int M,
    const float* __restrict__ nt, float* __restrict__ ot)
{
    float c[NBC][4];
    #pragma unroll
    for (int nb = 0; nb < NBC; nb++)
        #pragma unroll
        for (int i = 0; i < 4; i++) c[nb][i] = 0.f;

    const int R0 = (mb << 4) + (lane >> 2);
    const uint32_t abase = smb + rbuf_off
                         + (uint32_t)R0 * RPITCH + (((uint32_t)lane & 3) << 3);

    const int n0     = cq * (NBC * 8);
    const int n_half = n0 >> 6;
    const int nb0    = (n0 >> 3) & 7;
    const uint32_t bbase = smb + SM_BH
                         + (uint32_t)((n_half << 5) + lane) * 80 + (nb0 << 3);

    float2 cur[4], nxt[4];
    LDS64F(cur[0].x, cur[0].y, abase);                     // (R0,   k)
    LDS64F(cur[1].x, cur[1].y, abase + 32);                // (R0,   k+8)
    LDS64F(cur[2].x, cur[2].y, abase + 8 * RPITCH);        // (R0+8, k)
    LDS64F(cur[3].x, cur[3].y, abase + 8 * RPITCH + 32);   // (R0+8, k+8)

    #pragma unroll
    for (int ks = 0; ks < 8; ks++) {
        if (ks < 7) {
            const uint32_t an = abase + (((uint32_t)ks + 1) << 6);
            LDS64F(nxt[0].x, nxt[0].y, an);
            LDS64F(nxt[1].x, nxt[1].y, an + 32);
            LDS64F(nxt[2].x, nxt[2].y, an + 8 * RPITCH);
            LDS64F(nxt[3].x, nxt[3].y, an + 8 * RPITCH + 32);
        }

        // a-frag order: a0=(r,k) a1=(r+8,k) a2=(r,k+8) a3=(r+8,k+8)
        uint32_t ah[4], al[4];
        ah[0] = pack2h(cur[0].x, cur[0].y);
        ah[1] = pack2h(cur[2].x, cur[2].y);
        ah[2] = pack2h(cur[1].x, cur[1].y);
        ah[3] = pack2h(cur[3].x, cur[3].y);
        al[0] = pack2l(cur[0].x, cur[0].y);
        al[1] = pack2l(cur[2].x, cur[2].y);
        al[2] = pack2l(cur[1].x, cur[1].y);
        al[3] = pack2l(cur[3].x, cur[3].y);

        const uint32_t ba = bbase + (uint32_t)(ks << 1) * 32 * 80;
        #pragma unroll
        for (int jp = 0; jp < NBC / 2; jp++) {     // nb pair jp -> 2jp, 2jp+1
            uint32_t h[4], l[4];
            LDS128(h[0], h[1], h[2], h[3], ba + (jp << 4));
            LDS128(l[0], l[1], l[2], l[3], ba + (SM_BL - SM_BH) + (jp << 4));
            mma_bf16(c[2 * jp],     ah, h[0], h[1]);
            mma_bf16(c[2 * jp],     al, h[0], h[1]);
            mma_bf16(c[2 * jp],     ah, l[0], l[1]);
            mma_bf16(c[2 * jp + 1], ah, h[2], h[3]);
            mma_bf16(c[2 * jp + 1], al, h[2], h[3]);
            mma_bf16(c[2 * jp + 1], ah, l[2], l[3]);
        }

        cur[0] = nxt[0]; cur[1] = nxt[1];
        cur[2] = nxt[2]; cur[3] = nxt[3];
    }

    // epilogue for this unit: + node (direct LDG), relu, row mask, store
    const int rbase = (mb << 4) + (lane >> 2);
    const int cbase = n0 + ((lane & 3) << 1);
    #pragma unroll
    for (int half = 0; half < 2; half++) {
        int r  = rbase + (half << 3);
        bool on = r < M;
        int ci = half << 1;
        #pragma unroll
        for (int nb = 0; nb < NBC; nb++) {
            int col = cbase + (nb << 3);
            float2 o;
            if (on) {
                float2 nv = *(const float2*)(nt + r * F_DIM + col);
                o.x = fmaxf(c[nb][ci]     + nv.x, 0.f);
                o.y = fmaxf(c[nb][ci + 1] + nv.y, 0.f);
            } else {
                o.x = 0.f; o.y = 0.f;
            }
            *(float2*)(ot + r * F_DIM + col) = o;
        }
    }
}

__global__ __launch_bounds__(512, 1)
void blockend_mma(const float* __restrict__ node,
                  const float* __restrict__ resid,
                  const float* __restrict__ w,
                  const int*   __restrict__ mol_i32,
                  float* __restrict__ out,
                  int B)
{
    extern __shared__ char sm[];
    const uint32_t smb = smem_u32(sm);
    const int t    = threadIdx.x;
    const int wid  = t >> 5;
    const int lane = t & 31;

    const bool is_i64 = (mol_i32[1] == 0);

    // ---- prologue: stage molecule blockIdx.x into buf0; prefetch next id ----
    int p = 0;
    int b = blockIdx.x;
    int M_cur = 0;
    if (b < B) {
        M_cur = is_i64 ? mol_i32[4 * b] : mol_i32[2 * b];
        const char* src = (const char*)(resid + (size_t)b * A_DIM * K_DIM);
        #pragma unroll
        for (int i = 0; i < 8; i++) {
            int idx = t + (i << 9);            // 16B chunk id, 0..4095
            int r   = idx >> 5;                // row (warp-uniform)
            if (r < M_cur)
                CP_ASYNC16(smb + SM_R0 + r * RPITCH + ((idx & 31) << 4),
                           src + ((size_t)idx << 4));
        }
        CP_COMMIT();
    }
    if (t == 0) {
        int nb = atomicAdd(&g_next, 1);
        *(int*)(sm + SM_CTRL) = nb;            // slot[0]
    }

    // ---- one-time: w split into padded fragment layout Bh/Bl (validated R8) ----
    {
        const float4* wsrc = (const float4*)w;
        #pragma unroll
        for (int i = 0; i < 8; i++) {
            int idx4 = t + (i << 9);
            int k  = idx4 >> 5;
            int n0 = (idx4 & 31) << 2;
            float4 v = wsrc[idx4];
            float xs[4] = {v.x, v.y, v.z, v.w};
            int ks  = k >> 4;
            int rs  = ((((k >> 3) & 1)) << 2) + ((k & 1) << 1);
            int kl  = (k & 7) >> 1;
            #pragma unroll
            for (int j = 0; j < 4; j++) {
                int n   = n0 + j;
                int ln  = ((n & 7) << 2) + kl;
                int off = (((ks << 1) + (n >> 6)) * 32 + ln) * 80
                        + (((n >> 3) & 7) << 3) + rs;
                float x = xs[j];
                __nv_bfloat16 h = __float2bfloat16(x);
                *(__nv_bfloat16*)(sm + SM_BH + off) = h;
                *(__nv_bfloat16*)(sm + SM_BL + off) =
                    __float2bfloat16(x - __bfloat162float(h));
            }
        }
    }
    __syncthreads();   // w frags + slot[0] visible

    while (b < B) {
        const int M = M_cur;

        // ---- next molecule id (fetched one iteration ago into slot[p]) ----
        const int bn = *(int*)(sm + SM_CTRL + (p << 2));

        // ---- issue cp.async resid(bn) into buf[p^1] ----
        int M_nxt = 0;
        if (bn < B) {
            M_nxt = is_i64 ? mol_i32[4 * bn] : mol_i32[2 * bn];
            const uint32_t dbase = smb + (p ? SM_R0 : SM_R1);
            const char* src = (const char*)(resid + (size_t)bn * A_DIM * K_DIM);
            #pragma unroll
            for (int i = 0; i < 8; i++) {
                int idx = t + (i << 9);
                int r   = idx >> 5;
                if (r < M_nxt)
                    CP_ASYNC16(dbase + r * RPITCH + ((idx & 31) << 4),
                               src + ((size_t)idx << 4));
            }
        }
        CP_COMMIT();               // always commit: keeps group accounting uniform

        // ---- prefetch the id after bn into slot[p^1] (latency hidden) ----
        if (t == 0) {
            int nn = atomicAdd(&g_next, 1);
            *(int*)(sm + SM_CTRL + ((p ^ 1) << 2)) = nn;
        }

        CP_WAIT1();                // resid(b) arrived
        __syncthreads();           // also publishes slot[p^1] for next iter

        const int mA = (M + 15) >> 4;          // active m-blocks, 1..8
        const uint32_t rbuf = p ? SM_R1 : SM_R0;
        const float* nt = node + (size_t)b * A_DIM * F_DIM;
        float*       ot = out  + (size_t)b * A_DIM * F_DIM;

        // ---- zero-fill rows >= mA*16 first (STGs overlap compute below) ----
        {
            const int zr0 = mA << 4;
            const int n4  = (A_DIM - zr0) << 5;       // float4 count
            float4 z = make_float4(0.f, 0.f, 0.f, 0.f);
            float4* oz = (float4*)(ot + zr0 * F_DIM);
            for (int idx = t; idx < n4; idx += 512)
                oz[idx] = z;
        }

        // ---- adaptive warp tiling ----
        if (mA > 4) {             // ncg=2, NBC=8  (units = 2*mA <= 16)
            if (wid < 2 * mA)
                unit_compute<8>(smb, rbuf, lane, wid >> 1, wid & 1, M, nt, ot);
        } else if (mA > 2) {      // ncg=4, NBC=4  (units = 4*mA <= 16)
            if (wid < 4 * mA)
                unit_compute<4>(smb, rbuf, lane, wid >> 2, wid & 3, M, nt, ot);
        } else {                  // ncg=8, NBC=2  (units = 8*mA <= 16)
            if (wid < 8 * mA)
                unit_compute<2>(smb, rbuf, lane, wid >> 3, wid & 7, M, nt, ot);
        }
        __syncthreads();   // compute reads of buf[p] done before next overwrite

        p ^= 1;
        b = bn;
        M_cur = M_nxt;
    }
}

extern "C" void kernel_launch(void* const* d_in, const int* in_sizes, int n_in,
                              void* d_out, int out_size) {
    // size-based input identification (robust to metadata ordering)
    const float* node = nullptr;
    const float* res  = nullptr;
    const void*  wptr = nullptr;
    const void*  mptr = nullptr;

    for (int i = 0; i < n_in; i++) {
        if (in_sizes[i] >= (1 << 20)) {
            if (!node) node = (const float*)d_in[i];
            else if (!res) res = (const float*)d_in[i];
        }
    }
    for (int i = 0; i < n_in; i++) {
        if (in_sizes[i] < (1 << 20)) {
            if (!wptr && in_sizes[i] == F_DIM * K_DIM) { wptr = d_in[i]; continue; }
            if (!mptr && d_in[i] != wptr) mptr = d_in[i];
        }
    }
    if (!node) node = (const float*)d_in[0];
    if (!res)  res  = (const float*)d_in[1];
    if (!wptr) wptr = d_in[2];
    if (!mptr) mptr = d_in[3];

    int B = 0;
    for (int i = 0; i < n_in; i++)
        if (in_sizes[i] >= (1 << 20)) { B = in_sizes[i] / (A_DIM * F_DIM); break; }
    if (!B) B = 4096;

    int dev = 0, sms = 148;
    cudaGetDevice(&dev);
    cudaDeviceGetAttribute(&sms, cudaDevAttrMultiProcessorCount, dev);
    cudaFuncSetAttribute(blockend_mma, cudaFuncAttributeMaxDynamicSharedMemorySize,
                         SMEM_TOTAL);

    int grid = sms < B ? sms : B;
    reset_next<<<1, 32>>>(grid);
    blockend_mma<<<grid, 512, SMEM_TOTAL>>>(node, res, (const float*)wptr,
                                            (const int*)mptr, (float*)d_out, B);
}

// round 15
// speedup vs baseline: 1.1121x; 1.1121x over previous
#include <cuda_runtime.h>
#include <cuda_bf16.h>
#include <cstdint>

// out[b,a,f] = (a < M[b]) * relu( resid[b,a,:] @ w[:,f] + node[b,a,f] )
// B=4096, A=128, K=RF=128, F=128 fp32.
// SINGLE-PASS tf32 mma.sync m16n8k8 (cvt.rna), fp32 accum.
// 512 thr/CTA, adaptive warp tiling (ncg in {2,4,8}), static molecule striding.
// resid: double-buffered cp.async raw tile. node: direct LDG epilogue.

#define A_DIM 128
#define F_DIM 128
#define K_DIM 128

#define RPITCH 560                 // 140 floats: conflict-free rows
#define SM_R0  0
#define SM_R1  71680               // 128*560
#define SM_B   143360              // tf32 w frags: 16 ksteps x 8 jp x 32 lanes x 16B
#define SMEM_TOTAL 208896          // 143360 + 65536

__device__ __forceinline__ uint32_t smem_u32(const void* p) {
    uint32_t a;
    asm("{ .reg .u64 t; cvta.to.shared.u64 t, %1; cvt.u32.u64 %0, t; }" : "=r"(a) : "l"(p));
    return a;
}

#define CVT_TF32(d, f) asm("cvt.rna.tf32.f32 %0, %1;" : "=r"(d) : "f"(f))

#define LDS128(r0, r1, r2, r3, addr) \
    asm volatile("ld.shared.v4.b32 {%0,%1,%2,%3}, [%4];" \
                 : "=r"(r0), "=r"(r1), "=r"(r2), "=r"(r3) : "r"(addr))
#define LDSF(f0, addr) \
    asm volatile("ld.shared.f32 %0, [%1];" : "=f"(f0) : "r"(addr))
#define CP_ASYNC16(dst, src) \
    asm volatile("cp.async.cg.shared.global [%0], [%1], 16;" :: "r"(dst), "l"(src))
#define CP_COMMIT() asm volatile("cp.async.commit_group;" ::: "memory")
#define CP_WAIT1()  asm volatile("cp.async.wait_group 1;" ::: "memory")

__device__ __forceinline__ void mma_tf32(float* c, const uint32_t* a,
                                         uint32_t b0, uint32_t b1) {
    asm volatile(
        "mma.sync.aligned.m16n8k8.row.col.f32.tf32.tf32.f32 "
        "{%0,%1,%2,%3}, {%4,%5,%6,%7}, {%8,%9}, {%0,%1,%2,%3};"
        : "+f"(c[0]), "+f"(c[1]), "+f"(c[2]), "+f"(c[3])
        : "r"(a[0]), "r"(a[1]), "r"(a[2]), "r"(a[3]), "r"(b0), "r"(b1));
}

// One warp computes + stores a 16-row x NBC*8-col unit (single-pass tf32).
template<int NBC>
__device__ __forceinline__ void unit_compute(
    uint32_t smb, uint32_t rbuf_off, int lane, int mb, int cq, int M,
    const float* __restrict__ nt, float* __restrict__ ot)
{
    float c[NBC][4];
    #pragma unroll
    for (int nb = 0; nb < NBC; nb++)
        #pragma unroll
        for (int i = 0; i < 4; i++) c[nb][i] = 0.f;

    const int R0 = (mb << 4) + (lane >> 2);
    // A raw fp32: row R0 / R0+8, cols (lane&3)+8*ks and +4
    const uint32_t abase = smb + rbuf_off
                         + (uint32_t)R0 * RPITCH + (((uint32_t)lane & 3) << 2);

    // B frag layout: [kstep 16][jp 8][lane 32][16B = {b0,b1}nb_even,{b0,b1}nb_odd]
    const int jp0 = cq * (NBC / 2);
    const uint32_t bbase = smb + SM_B + (uint32_t)(jp0 * 32 + lane) * 16;

    #pragma unroll
    for (int ks = 0; ks < 16; ks++) {
        // A: 4 scalars, conflict-free (rows 12r-mod32 spread + col 0..3)
        float f0, f1, f2, f3;
        const uint32_t ak = abase + ((uint32_t)ks << 5);
        LDSF(f0, ak);                       // (R0,   k)
        LDSF(f1, ak + 8 * RPITCH);          // (R0+8, k)
        LDSF(f2, ak + 16);                  // (R0,   k+4)
        LDSF(f3, ak + 8 * RPITCH + 16);     // (R0+8, k+4)

        uint32_t a[4];
        CVT_TF32(a[0], f0);
        CVT_TF32(a[1], f1);
        CVT_TF32(a[2], f2);
        CVT_TF32(a[3], f3);

        const uint32_t ba = bbase + ((uint32_t)ks << 12);   // ks * 8*32*16
        #pragma unroll
        for (int jp = 0; jp < NBC / 2; jp++) {
            uint32_t v[4];
            LDS128(v[0], v[1], v[2], v[3], ba + ((uint32_t)jp << 9));
            mma_tf32(c[2 * jp],     a, v[0], v[1]);
            mma_tf32(c[2 * jp + 1], a, v[2], v[3]);
        }
    }

    // epilogue for this unit: + node (direct LDG), relu, row mask, store
    const int rbase = (mb << 4) + (lane >> 2);
    const int cbase = cq * (NBC * 8) + ((lane & 3) << 1);
    #pragma unroll
    for (int half = 0; half < 2; half++) {
        int r  = rbase + (half << 3);
        bool on = r < M;
        int ci = half << 1;
        #pragma unroll
        for (int nb = 0; nb < NBC; nb++) {
            int col = cbase + (nb << 3);
            float2 o;
            if (on) {
                float2 nv = *(const float2*)(nt + r * F_DIM + col);
                o.x = fmaxf(c[nb][ci]     + nv.x, 0.f);
                o.y = fmaxf(c[nb][ci + 1] + nv.y, 0.f);
            } else {
                o.x = 0.f; o.y = 0.f;
            }
            *(float2*)(ot + r * F_DIM + col) = o;
        }
    }
}

__global__ __launch_bounds__(512, 1)
void blockend_mma(const float* __restrict__ node,
                  const float* __restrict__ resid,
                  const float* __restrict__ w,
                  const int*   __restrict__ mol_i32,
                  float* __restrict__ out,
                  int B)
{
    extern __shared__ char sm[];
    const uint32_t smb = smem_u32(sm);
    const int t    = threadIdx.x;
    const int wid  = t >> 5;
    const int lane = t & 31;

    const bool is_i64 = (mol_i32[1] == 0);

    // ---- prologue: cp.async resid(first tile) into buf0 ----
    int p = 0;
    const int b0 = blockIdx.x;
    int M_cur = 0;
    if (b0 < B) {
        M_cur = is_i64 ? mol_i32[4 * b0] : mol_i32[2 * b0];
        const char* src = (const char*)(resid + (size_t)b0 * A_DIM * K_DIM);
        #pragma unroll
        for (int i = 0; i < 8; i++) {
            int idx = t + (i << 9);            // 16B chunk id, 0..4095
            int r   = idx >> 5;                // row (warp-uniform)
            if (r < M_cur)
                CP_ASYNC16(smb + SM_R0 + r * RPITCH + ((idx & 31) << 4),
                           src + ((size_t)idx << 4));
        }
        CP_COMMIT();
    }

    // ---- one-time: w -> tf32 frag layout ----
    // element (k,n): kstep=k>>3, kin=k&7, reg=kin>>2, tig=kin&3,
    //   lane=(n&7)*4+tig, jp=n>>4, nbin=(n>>3)&1
    //   float_idx = ((kstep*8 + jp)*32 + lane)*4 + nbin*2 + reg
    {
        const float4* wsrc = (const float4*)w;
        #pragma unroll
        for (int i = 0; i < 8; i++) {
            int idx4 = t + (i << 9);
            int k  = idx4 >> 5;
            int n0 = (idx4 & 31) << 2;
            float4 v = wsrc[idx4];
            float xs[4] = {v.x, v.y, v.z, v.w};
            int kstep = k >> 3;
            int reg   = (k >> 2) & 1;
            int tig   = k & 3;
            #pragma unroll
            for (int j = 0; j < 4; j++) {
                int n    = n0 + j;
                int ln   = ((n & 7) << 2) + tig;
                int fidx = (((kstep << 3) + (n >> 4)) * 32 + ln) * 4
                         + (((n >> 3) & 1) << 1) + reg;
                uint32_t tv;
                CVT_TF32(tv, xs[j]);
                *(uint32_t*)(sm + SM_B + (fidx << 2)) = tv;
            }
        }
    }

    for (int b = b0; b < B; b += gridDim.x) {
        const int M = M_cur;

        // ---- issue cp.async resid(next tile) into buf[p^1] ----
        const int bn = b + gridDim.x;
        int M_nxt = 0;
        if (bn < B) {
            M_nxt = is_i64 ? mol_i32[4 * bn] : mol_i32[2 * bn];
            const uint32_t dbase = smb + (p ? SM_R0 : SM_R1);
            const char* src = (const char*)(resid + (size_t)bn * A_DIM * K_DIM);
            #pragma unroll
            for (int i = 0; i < 8; i++) {
                int idx = t + (i << 9);
                int r   = idx >> 5;
                if (r < M_nxt)
                    CP_ASYNC16(dbase + r * RPITCH + ((idx & 31) << 4),
                               src + ((size_t)idx << 4));
            }
        }
        CP_COMMIT();               // always commit: keeps group accounting uniform

        CP_WAIT1();                // resid(b) arrived
        __syncthreads();

        const int mA = (M + 15) >> 4;          // active m-blocks, 1..8
        const uint32_t rbuf = p ? SM_R1 : SM_R0;
        const float* nt = node + (size_t)b * A_DIM * F_DIM;
        float*       ot = out  + (size_t)b * A_DIM * F_DIM;

        // ---- zero-fill rows >= mA*16 first (STGs overlap compute below) ----
        {
            const int zr0 = mA << 4;
            const int n4  = (A_DIM - zr0) << 5;       // float4 count
            float4 z = make_float4(0.f, 0.f, 0.f, 0.f);
            float4* oz = (float4*)(ot + zr0 * F_DIM);
            for (int idx = t; idx < n4; idx += 512)
                oz[idx] = z;
        }

        // ---- adaptive warp tiling ----
        if (mA > 4) {             // ncg=2, NBC=8
            if (wid < 2 * mA)
                unit_compute<8>(smb, rbuf, lane, wid >> 1, wid & 1, M, nt, ot);
        } else if (mA > 2) {      // ncg=4, NBC=4
            if (wid < 4 * mA)
                unit_compute<4>(smb, rbuf, lane, wid >> 2, wid & 3, M, nt, ot);
        } else {                  // ncg=8, NBC=2
            if (wid < 8 * mA)
                unit_compute<2>(smb, rbuf, lane, wid >> 3, wid & 7, M, nt, ot);
        }
        __syncthreads();   // compute reads of buf[p] done before next overwrite

        p ^= 1;
        M_cur = M_nxt;
    }
}

extern "C" void kernel_launch(void* const* d_in, const int* in_sizes, int n_in,
                              void* d_out, int out_size) {
    // size-based input identification (robust to metadata ordering)
    const float* node = nullptr;
    const float* res  = nullptr;
    const void*  wptr = nullptr;
    const void*  mptr = nullptr;

    for (int i = 0; i < n_in; i++) {
        if (in_sizes[i] >= (1 << 20)) {
            if (!node) node = (const float*)d_in[i];
            else if (!res) res = (const float*)d_in[i];
        }
    }
    for (int i = 0; i < n_in; i++) {
        if (in_sizes[i] < (1 << 20)) {
            if (!wptr && in_sizes[i] == F_DIM * K_DIM) { wptr = d_in[i]; continue; }
            if (!mptr && d_in[i] != wptr) mptr = d_in[i];
        }
    }
    if (!node) node = (const float*)d_in[0];
    if (!res)  res  = (const float*)d_in[1];
    if (!wptr) wptr = d_in[2];
    if (!mptr) mptr = d_in[3];

    int B = 0;
    for (int i = 0; i < n_in; i++)
        if (in_sizes[i] >= (1 << 20)) { B = in_sizes[i] / (A_DIM * F_DIM); break; }
    if (!B) B = 4096;

    int dev = 0, sms = 148;
    cudaGetDevice(&dev);
    cudaDeviceGetAttribute(&sms, cudaDevAttrMultiProcessorCount, dev);
    cudaFuncSetAttribute(blockend_mma, cudaFuncAttributeMaxDynamicSharedMemorySize,
                         SMEM_TOTAL);

    int grid = sms < B ? sms : B;
    blockend_mma<<<grid, 512, SMEM_TOTAL>>>(node, res, (const float*)wptr,
                                            (const int*)mptr, (float*)d_out, B);
}

// round 16
// speedup vs baseline: 1.1259x; 1.0124x over previous
#include <cuda_runtime.h>
#include <cuda_bf16.h>
#include <cstdint>

// out[b,a,f] = (a < M[b]) * relu( resid[b,a,:] @ w[:,f] + node[b,a,f] )
// B=4096, A=128, K=RF=128, F=128 fp32.
// SINGLE-PASS tf32 mma.sync m16n8k8 (cvt.rna), fp32 accum.
// Warp-autonomous: unit = (molecule, m-block) = 16 rows x 128 cols per warp,
// dynamic scheduling via global atomic, NO CTA barriers in steady state.
// A: direct LDG (1-ks pipeline + L2 prefetch). B(w) frags in smem (64KB).

#define A_DIM 128
#define F_DIM 128
#define K_DIM 128

#define SM_B 0                     // tf32 w frags: 16 ksteps x 8 jp x 32 lanes x 16B
#define SMEM_TOTAL 65536

__device__ int g_next;

__global__ void reset_next(int v) {
    if (threadIdx.x == 0 && blockIdx.x == 0) g_next = v;
}

__device__ __forceinline__ uint32_t smem_u32(const void* p) {
    uint32_t a;
    asm("{ .reg .u64 t; cvta.to.shared.u64 t, %1; cvt.u32.u64 %0, t; }" : "=r"(a) : "l"(p));
    return a;
}

#define CVT_TF32(d, f) asm("cvt.rna.tf32.f32 %0, %1;" : "=r"(d) : "f"(f))
#define LDS128(r0, r1, r2, r3, addr) \
    asm volatile("ld.shared.v4.b32 {%0,%1,%2,%3}, [%4];" \
                 : "=r"(r0), "=r"(r1), "=r"(r2), "=r"(r3) : "r"(addr))
#define PREFETCH_L2(ptr) \
    asm volatile("prefetch.global.L2 [%0];" :: "l"(ptr))

__device__ __forceinline__ void mma_tf32(float* c, const uint32_t* a,
                                         uint32_t b0, uint32_t b1) {
    asm volatile(
        "mma.sync.aligned.m16n8k8.row.col.f32.tf32.tf32.f32 "
        "{%0,%1,%2,%3}, {%4,%5,%6,%7}, {%8,%9}, {%0,%1,%2,%3};"
        : "+f"(c[0]), "+f"(c[1]), "+f"(c[2]), "+f"(c[3])
        : "r"(a[0]), "r"(a[1]), "r"(a[2]), "r"(a[3]), "r"(b0), "r"(b1));
}

__global__ __launch_bounds__(512, 1)
void blockend_mma(const float* __restrict__ node,
                  const float* __restrict__ resid,
                  const float* __restrict__ w,
                  const int*   __restrict__ mol_i32,
                  float* __restrict__ out,
                  int B)
{
    extern __shared__ char sm[];
    const uint32_t smb = smem_u32(sm);
    const int t    = threadIdx.x;
    const int wid  = t >> 5;
    const int lane = t & 31;

    const bool is_i64 = (mol_i32[1] == 0);
    const int  NU    = B << 3;                 // units = 8 per molecule

    // ---- one-time: w -> tf32 frag layout (validated R15) ----
    // element (k,n): kstep=k>>3, reg=(k>>2)&1, tig=k&3, lane=(n&7)*4+tig,
    //   jp=n>>4, nbin=(n>>3)&1
    //   float_idx = ((kstep*8 + jp)*32 + lane)*4 + nbin*2 + reg
    {
        const float4* wsrc = (const float4*)w;
        #pragma unroll
        for (int i = 0; i < 8; i++) {
            int idx4 = t + (i << 9);
            int k  = idx4 >> 5;
            int n0 = (idx4 & 31) << 2;
            float4 v = wsrc[idx4];
            float xs[4] = {v.x, v.y, v.z, v.w};
            int kstep = k >> 3;
            int reg   = (k >> 2) & 1;
            int tig   = k & 3;
            #pragma unroll
            for (int j = 0; j < 4; j++) {
                int n    = n0 + j;
                int ln   = ((n & 7) << 2) + tig;
                int fidx = (((kstep << 3) + (n >> 4)) * 32 + ln) * 4
                         + (((n >> 3) & 1) << 1) + reg;
                uint32_t tv;
                CVT_TF32(tv, xs[j]);
                *(uint32_t*)(sm + SM_B + (fidx << 2)) = tv;
            }
        }
    }
    __syncthreads();     // only barrier; B frags immutable afterwards

    // ---- warp-autonomous unit loop ----
    int u = blockIdx.x * 16 + wid;            // initial unit for this warp

    while (u < NU) {
        // fetch NEXT unit id now (latency hidden behind this unit's work)
        int u_next;
        if (lane == 0) u_next = atomicAdd(&g_next, 1);
        u_next = __shfl_sync(0xffffffffu, u_next, 0);

        const int b  = u >> 3;
        const int mb = u & 7;
        const int M  = is_i64 ? mol_i32[4 * b] : mol_i32[2 * b];
        const int r0 = mb << 4;               // unit rows r0 .. r0+15

        float* ot = out + ((size_t)b * A_DIM + r0) * F_DIM;

        if (r0 >= M) {
            // ---- zero-fill unit: 16 rows x 128 cols ----
            float4 z = make_float4(0.f, 0.f, 0.f, 0.f);
            float4* o4 = (float4*)ot;
            #pragma unroll
            for (int i = 0; i < 16; i++)      // 512 float4 / 32 lanes
                o4[lane + (i << 5)] = z;
        } else {
            // ---- compute unit ----
            const int R0 = r0 + (lane >> 2);
            const int c0 = lane & 3;
            const float* ar0 = resid + ((size_t)b * A_DIM + R0) * K_DIM + c0;
            const float* ar1 = ar0 + 8 * K_DIM;
            const float* nt  = node + ((size_t)b * A_DIM + r0) * F_DIM;

            // L2 prefetch: A strip rows (R0, R0+8) + node rows — 128B lines
            {
                const char* pa0 = (const char*)(resid + ((size_t)b * A_DIM + R0) * K_DIM) + ((lane & 3) << 7);
                const char* pn0 = (const char*)(node  + ((size_t)b * A_DIM + R0) * F_DIM) + ((lane & 3) << 7);
                PREFETCH_L2(pa0);
                PREFETCH_L2(pa0 + 8 * K_DIM * 4);
                PREFETCH_L2(pn0);
                PREFETCH_L2(pn0 + 8 * F_DIM * 4);
            }

            float c[16][4];
            #pragma unroll
            for (int nb = 0; nb < 16; nb++)
                #pragma unroll
                for (int i = 0; i < 4; i++) c[nb][i] = 0.f;

            // A pipeline: cur = (R0,k),(R0+8,k),(R0,k+4),(R0+8,k+4), k = c0+8ks
            float cur0 = ar0[0], cur1 = ar1[0], cur2 = ar0[4], cur3 = ar1[4];

            #pragma unroll
            for (int ks = 0; ks < 16; ks++) {
                float nx0, nx1, nx2, nx3;
                if (ks < 15) {
                    const int kb = (ks + 1) << 3;
                    nx0 = ar0[kb];     nx1 = ar1[kb];
                    nx2 = ar0[kb + 4]; nx3 = ar1[kb + 4];
                }

                uint32_t a[4];
                CVT_TF32(a[0], cur0);
                CVT_TF32(a[1], cur1);
                CVT_TF32(a[2], cur2);
                CVT_TF32(a[3], cur3);

                const uint32_t ba = smb + SM_B
                                  + ((uint32_t)(ks << 3) * 32 + (uint32_t)lane) * 16;
                #pragma unroll
                for (int jp = 0; jp < 8; jp++) {
                    uint32_t v[4];
                    LDS128(v[0], v[1], v[2], v[3], ba + ((uint32_t)jp << 9));
                    mma_tf32(c[2 * jp],     a, v[0], v[1]);
                    mma_tf32(c[2 * jp + 1], a, v[2], v[3]);
                }

                cur0 = nx0; cur1 = nx1; cur2 = nx2; cur3 = nx3;
            }

            // ---- epilogue: + node, relu, row mask, store ----
            const int rb = lane >> 2;
            const int cb = (lane & 3) << 1;
            #pragma unroll
            for (int half = 0; half < 2; half++) {
                int r  = rb + (half << 3);
                bool on = (r0 + r) < M;
                int ci = half << 1;
                #pragma unroll
                for (int nb = 0; nb < 16; nb++) {
                    int col = cb + (nb << 3);
                    float2 o;
                    if (on) {
                        float2 nv = *(const float2*)(nt + r * F_DIM + col);
                        o.x = fmaxf(c[nb][ci]     + nv.x, 0.f);
                        o.y = fmaxf(c[nb][ci + 1] + nv.y, 0.f);
                    } else {
                        o.x = 0.f; o.y = 0.f;
                    }
                    *(float2*)(ot + r * F_DIM + col) = o;
                }
            }
        }

        u = u_next;
    }
}

extern "C" void kernel_launch(void* const* d_in, const int* in_sizes, int n_in,
                              void* d_out, int out_size) {
    // size-based input identification (robust to metadata ordering)
    const float* node = nullptr;
    const float* res  = nullptr;
    const void*  wptr = nullptr;
    const void*  mptr = nullptr;

    for (int i = 0; i < n_in; i++) {
        if (in_sizes[i] >= (1 << 20)) {
            if (!node) node = (const float*)d_in[i];
            else if (!res) res = (const float*)d_in[i];
        }
    }
    for (int i = 0; i < n_in; i++) {
        if (in_sizes[i] < (1 << 20)) {
            if (!wptr && in_sizes[i] == F_DIM * K_DIM) { wptr = d_in[i]; continue; }
            if (!mptr && d_in[i] != wptr) mptr = d_in[i];
        }
    }
    if (!node) node = (const float*)d_in[0];
    if (!res)  res  = (const float*)d_in[1];
    if (!wptr) wptr = d_in[2];
    if (!mptr) mptr = d_in[3];

    int B = 0;
    for (int i = 0; i < n_in; i++)
        if (in_sizes[i] >= (1 << 20)) { B = in_sizes[i] / (A_DIM * F_DIM); break; }
    if (!B) B = 4096;

    int dev = 0, sms = 148;
    cudaGetDevice(&dev);
    cudaDeviceGetAttribute(&sms, cudaDevAttrMultiProcessorCount, dev);
    cudaFuncSetAttribute(blockend_mma, cudaFuncAttributeMaxDynamicSharedMemorySize,
                         SMEM_TOTAL);

    int grid = sms;
    reset_next<<<1, 32>>>(grid * 16);         // next unit after the statically-seeded ones
    blockend_mma<<<grid, 512, SMEM_TOTAL>>>(node, res, (const float*)wptr,
                                            (const int*)mptr, (float*)d_out, B);
}

// round 17
// speedup vs baseline: 1.1586x; 1.0290x over previous
#include <cuda_runtime.h>
#include <cuda_bf16.h>
#include <cstdint>

// out[b,a,f] = (a < M[b]) * relu( resid[b,a,:] @ w[:,f] + node[b,a,f] )
// B=4096, A=128, K=RF=128, F=128 fp32.
// SINGLE-PASS tf32 mma.sync m16n8k8 (cvt.rna), fp32 accum.
// Warp-autonomous units (16 rows x 128 cols), dynamic scheduling, no steady-state
// CTA barriers. A: per-warp smem staging via coalesced cp.async (2 halves,
// per-thread wait_group pipelining). B(w) frags in smem (64KB).

#define A_DIM 128
#define F_DIM 128
#define K_DIM 128

#define SM_B     0                 // tf32 w frags: 16 ksteps x 8 jp x 32 lanes x 16B
#define SM_A     65536             // per-warp A buffers
#define AW_PITCH 528               // 132 floats/row: bank = (4r+c) mod 32, conflict-free
#define AW_BUF   8448              // 16 rows * 528B
#define SMEM_TOTAL 200704          // 65536 + 16*8448

__device__ int g_next;

__global__ void reset_next(int v) {
    if (threadIdx.x == 0 && blockIdx.x == 0) g_next = v;
}

__device__ __forceinline__ uint32_t smem_u32(const void* p) {
    uint32_t a;
    asm("{ .reg .u64 t; cvta.to.shared.u64 t, %1; cvt.u32.u64 %0, t; }" : "=r"(a) : "l"(p));
    return a;
}

#define CVT_TF32(d, f) asm("cvt.rna.tf32.f32 %0, %1;" : "=r"(d) : "f"(f))
#define LDS128(r0, r1, r2, r3, addr) \
    asm volatile("ld.shared.v4.b32 {%0,%1,%2,%3}, [%4];" \
                 : "=r"(r0), "=r"(r1), "=r"(r2), "=r"(r3) : "r"(addr))
#define LDSF(f0, addr) \
    asm volatile("ld.shared.f32 %0, [%1];" : "=f"(f0) : "r"(addr))
#define CP_ASYNC16(dst, src) \
    asm volatile("cp.async.cg.shared.global [%0], [%1], 16;" :: "r"(dst), "l"(src))
#define CP_COMMIT() asm volatile("cp.async.commit_group;" ::: "memory")
#define CP_WAIT1()  asm volatile("cp.async.wait_group 1;" ::: "memory")
#define CP_WAIT0()  asm volatile("cp.async.wait_group 0;" ::: "memory")
#define PREFETCH_L2(ptr) \
    asm volatile("prefetch.global.L2 [%0];" :: "l"(ptr))

__device__ __forceinline__ void mma_tf32(float* c, const uint32_t* a,
                                         uint32_t b0, uint32_t b1) {
    asm volatile(
        "mma.sync.aligned.m16n8k8.row.col.f32.tf32.tf32.f32 "
        "{%0,%1,%2,%3}, {%4,%5,%6,%7}, {%8,%9}, {%0,%1,%2,%3};"
        : "+f"(c[0]), "+f"(c[1]), "+f"(c[2]), "+f"(c[3])
        : "r"(a[0]), "r"(a[1]), "r"(a[2]), "r"(a[3]), "r"(b0), "r"(b1));
}

__global__ __launch_bounds__(512, 1)
void blockend_mma(const float* __restrict__ node,
                  const float* __restrict__ resid,
                  const float* __restrict__ w,
                  const int*   __restrict__ mol_i32,
                  float* __restrict__ out,
                  int B)
{
    extern __shared__ char sm[];
    const uint32_t smb = smem_u32(sm);
    const int t    = threadIdx.x;
    const int wid  = t >> 5;
    const int lane = t & 31;

    const bool is_i64 = (mol_i32[1] == 0);
    const int  NU    = B << 3;                 // 8 units per molecule

    // ---- one-time: w -> tf32 frag layout (validated R15) ----
    {
        const float4* wsrc = (const float4*)w;
        #pragma unroll
        for (int i = 0; i < 8; i++) {
            int idx4 = t + (i << 9);
            int k  = idx4 >> 5;
            int n0 = (idx4 & 31) << 2;
            float4 v = wsrc[idx4];
            float xs[4] = {v.x, v.y, v.z, v.w};
            int kstep = k >> 3;
            int reg   = (k >> 2) & 1;
            int tig   = k & 3;
            #pragma unroll
            for (int j = 0; j < 4; j++) {
                int n    = n0 + j;
                int ln   = ((n & 7) << 2) + tig;
                int fidx = (((kstep << 3) + (n >> 4)) * 32 + ln) * 4
                         + (((n >> 3) & 1) << 1) + reg;
                uint32_t tv;
                CVT_TF32(tv, xs[j]);
                *(uint32_t*)(sm + SM_B + (fidx << 2)) = tv;
            }
        }
    }
    __syncthreads();     // only barrier; B frags immutable afterwards

    const uint32_t abuf   = smb + SM_A + (uint32_t)wid * AW_BUF;
    const uint32_t abase0 = abuf + (uint32_t)(lane >> 2) * AW_PITCH
                          + (((uint32_t)lane & 3) << 2);
    const uint32_t abase1 = abase0 + 8 * AW_PITCH;

    // ---- warp-autonomous unit loop ----
    int u = blockIdx.x * 16 + wid;

    while (u < NU) {
        int u_next;
        if (lane == 0) u_next = atomicAdd(&g_next, 1);
        u_next = __shfl_sync(0xffffffffu, u_next, 0);

        const int b  = u >> 3;
        const int mb = u & 7;
        const int M  = is_i64 ? mol_i32[4 * b] : mol_i32[2 * b];
        const int r0 = mb << 4;

        float* ot = out + ((size_t)b * A_DIM + r0) * F_DIM;

        if (r0 >= M) {
            // ---- zero-fill unit ----
            float4 z = make_float4(0.f, 0.f, 0.f, 0.f);
            float4* o4 = (float4*)ot;
            #pragma unroll
            for (int i = 0; i < 16; i++)
                o4[lane + (i << 5)] = z;
        } else {
            const char* srcb = (const char*)(resid + ((size_t)b * A_DIM + r0) * K_DIM);
            const float* nt  = node + ((size_t)b * A_DIM + r0) * F_DIM;

            // ---- stage A strip: coalesced cp.async, 2 halves ----
            #pragma unroll
            for (int i = 0; i < 8; i++) {           // half 1: k 0..63 of all rows
                int idx = lane + (i << 5);          // 0..255
                int r   = idx >> 4;
                int ch  = idx & 15;                 // 16B chunk 0..15
                CP_ASYNC16(abuf + (uint32_t)r * AW_PITCH + ((uint32_t)ch << 4),
                           srcb + r * 512 + (ch << 4));
            }
            CP_COMMIT();
            #pragma unroll
            for (int i = 0; i < 8; i++) {           // half 2: k 64..127
                int idx = lane + (i << 5);
                int r   = idx >> 4;
                int ch  = (idx & 15) + 16;
                CP_ASYNC16(abuf + (uint32_t)r * AW_PITCH + ((uint32_t)ch << 4),
                           srcb + r * 512 + (ch << 4));
            }
            CP_COMMIT();

            // L2 prefetch node rows (epilogue)
            {
                const char* pn0 = (const char*)nt + ((lane & 15) << 7);
                PREFETCH_L2(pn0);
                PREFETCH_L2(pn0 + 8 * F_DIM * 4);
            }

            float c[16][4];
            #pragma unroll
            for (int nb = 0; nb < 16; nb++)
                #pragma unroll
                for (int i = 0; i < 4; i++) c[nb][i] = 0.f;

            CP_WAIT1();                             // half 1 landed
            #pragma unroll
            for (int ks = 0; ks < 16; ks++) {
                if (ks == 8) CP_WAIT0();            // half 2 landed

                float f0, f1, f2, f3;
                const uint32_t ak = (uint32_t)ks << 5;      // 8 floats per ks
                LDSF(f0, abase0 + ak);              // (R0,   k)
                LDSF(f1, abase1 + ak);              // (R0+8, k)
                LDSF(f2, abase0 + ak + 16);         // (R0,   k+4)
                LDSF(f3, abase1 + ak + 16);         // (R0+8, k+4)

                uint32_t a[4];
                CVT_TF32(a[0], f0);
                CVT_TF32(a[1], f1);
                CVT_TF32(a[2], f2);
                CVT_TF32(a[3], f3);

                const uint32_t ba = smb + SM_B
                                  + ((uint32_t)(ks << 3) * 32 + (uint32_t)lane) * 16;
                #pragma unroll
                for (int jp = 0; jp < 8; jp++) {
                    uint32_t v[4];
                    LDS128(v[0], v[1], v[2], v[3], ba + ((uint32_t)jp << 9));
                    mma_tf32(c[2 * jp],     a, v[0], v[1]);
                    mma_tf32(c[2 * jp + 1], a, v[2], v[3]);
                }
            }

            // ---- epilogue: + node, relu, row mask, store ----
            const int rb = lane >> 2;
            const int cb = (lane & 3) << 1;
            #pragma unroll
            for (int half = 0; half < 2; half++) {
                int r  = rb + (half << 3);
                bool on = (r0 + r) < M;
                int ci = half << 1;
                #pragma unroll
                for (int nb = 0; nb < 16; nb++) {
                    int col = cb + (nb << 3);
                    float2 o;
                    if (on) {
                        float2 nv = *(const float2*)(nt + r * F_DIM + col);
                        o.x = fmaxf(c[nb][ci]     + nv.x, 0.f);
                        o.y = fmaxf(c[nb][ci + 1] + nv.y, 0.f);
                    } else {
                        o.x = 0.f; o.y = 0.f;
                    }
                    *(float2*)(ot + r * F_DIM + col) = o;
                }
            }
        }

        u = u_next;
    }
}

extern "C" void kernel_launch(void* const* d_in, const int* in_sizes, int n_in,
                              void* d_out, int out_size) {
    // size-based input identification (robust to metadata ordering)
    const float* node = nullptr;
    const float* res  = nullptr;
    const void*  wptr = nullptr;
    const void*  mptr = nullptr;

    for (int i = 0; i < n_in; i++) {
        if (in_sizes[i] >= (1 << 20)) {
            if (!node) node = (const float*)d_in[i];
            else if (!res) res = (const float*)d_in[i];
        }
    }
    for (int i = 0; i < n_in; i++) {
        if (in_sizes[i] < (1 << 20)) {
            if (!wptr && in_sizes[i] == F_DIM * K_DIM) { wptr = d_in[i]; continue; }
            if (!mptr && d_in[i] != wptr) mptr = d_in[i];
        }
    }
    if (!node) node = (const float*)d_in[0];
    if (!res)  res  = (const float*)d_in[1];
    if (!wptr) wptr = d_in[2];
    if (!mptr) mptr = d_in[3];

    int B = 0;
    for (int i = 0; i < n_in; i++)
        if (in_sizes[i] >= (1 << 20)) { B = in_sizes[i] / (A_DIM * F_DIM); break; }
    if (!B) B = 4096;

    int dev = 0, sms = 148;
    cudaGetDevice(&dev);
    cudaDeviceGetAttribute(&sms, cudaDevAttrMultiProcessorCount, dev);
    cudaFuncSetAttribute(blockend_mma, cudaFuncAttributeMaxDynamicSharedMemorySize,
                         SMEM_TOTAL);

    int grid = sms;
    reset_next<<<1, 32>>>(grid * 16);
    blockend_mma<<<grid, 512, SMEM_TOTAL>>>(node, res, (const float*)wptr,
                                            (const int*)mptr, (float*)d_out, B);
}